// round 8
// baseline (speedup 1.0000x reference)
#include <cuda_runtime.h>
#include <cuda_bf16.h>
#include <cstdint>

#define B_ 256
#define T_ 512
#define D_ 128
#define H_ 128
#define G_ 384          // 3H, gate order z|r|h
#define BT_ (B_*T_)

__device__ float g_xp[(size_t)BT_ * G_];             // 201 MB scratch
__device__ float g_h0[(size_t)BT_ * H_];             // 67 MB scratch
__device__ __nv_bfloat16 g_wth[(size_t)G_ * 128];    // W^T hi
__device__ __nv_bfloat16 g_wtl[(size_t)G_ * 128];    // W^T lo

typedef unsigned long long u64;

static __device__ __forceinline__ u64 pack2(float a, float b) {
    u64 r; asm("mov.b64 %0, {%1, %2};" : "=l"(r) : "f"(a), "f"(b)); return r;
}
static __device__ __forceinline__ void unpack2(u64 v, float &a, float &b) {
    asm("mov.b64 {%0, %1}, %2;" : "=f"(a), "=f"(b) : "l"(v));
}
static __device__ __forceinline__ u64 fma2(u64 a, u64 b, u64 c) {
    u64 d; asm("fma.rn.f32x2 %0, %1, %2, %3;" : "=l"(d) : "l"(a), "l"(b), "l"(c)); return d;
}
static __device__ __forceinline__ float sigf(float a) {
    return __fdividef(1.0f, 1.0f + __expf(-a));
}
static __device__ __forceinline__ float tanh_fast(float a) {
    return __fdividef(2.0f, 1.0f + __expf(-2.0f * a)) - 1.0f;
}
static __device__ __forceinline__ uint32_t smem_u32(const void* p) {
    uint32_t a;
    asm("{ .reg .u64 t; cvta.to.shared.u64 t, %1; cvt.u32.u64 %0, t; }"
        : "=r"(a) : "l"(p));
    return a;
}
static __device__ __forceinline__ void ldm_x4(uint32_t &r0, uint32_t &r1,
                                              uint32_t &r2, uint32_t &r3,
                                              uint32_t addr) {
    asm volatile("ldmatrix.sync.aligned.m8n8.x4.shared.b16 {%0,%1,%2,%3}, [%4];"
                 : "=r"(r0), "=r"(r1), "=r"(r2), "=r"(r3) : "r"(addr));
}
static __device__ __forceinline__ void mma_bf16(float* d, const uint32_t* a,
                                                const uint32_t* b) {
    asm volatile(
        "mma.sync.aligned.m16n8k16.row.col.f32.bf16.bf16.f32 "
        "{%0,%1,%2,%3}, {%4,%5,%6,%7}, {%8,%9}, {%0,%1,%2,%3};"
        : "+f"(d[0]), "+f"(d[1]), "+f"(d[2]), "+f"(d[3])
        : "r"(a[0]), "r"(a[1]), "r"(a[2]), "r"(a[3]), "r"(b[0]), "r"(b[1]));
}

// ---------------------------------------------------------------------------
// prep: W [128, 384] -> W^T hi/lo bf16 splits [384][128]
// ---------------------------------------------------------------------------
__global__ void prep_w(const float* __restrict__ W,
                       __nv_bfloat16* __restrict__ wth,
                       __nv_bfloat16* __restrict__ wtl)
{
    int idx = blockIdx.x * blockDim.x + threadIdx.x;
    if (idx >= G_ * 128) return;
    int j = idx >> 7, k = idx & 127;
    float w = W[k * G_ + j];
    __nv_bfloat16 h = __float2bfloat16_rn(w);
    wth[idx] = h;
    wtl[idx] = __float2bfloat16_rn(w - __bfloat162float(h));
}

// ---------------------------------------------------------------------------
// proj_mma: out[n,g] = sum_k x[n,k] W[k,g] + bias[g] via mma.sync bf16 x3.
// CTA tile 128(M) x 128(N) x 128(K). A/B hi/lo in smem, pitch 136 bf16
// (272 B rows -> conflict-free ldmatrix). 8 warps = 2(M) x 4(N);
// warp tile 64x32. grid = (BT/128, 3).
// ---------------------------------------------------------------------------
#define PITCH 136
#define SM_TILE (128 * PITCH)                  // bf16 elems per array
#define SMEM_PROJ (4 * SM_TILE * 2)            // bytes = 139264

__global__ __launch_bounds__(256, 1)
void proj_mma(const float* __restrict__ x,
              const __nv_bfloat16* __restrict__ wth,
              const __nv_bfloat16* __restrict__ wtl,
              const float* __restrict__ bias, float* __restrict__ out)
{
    extern __shared__ __align__(16) __nv_bfloat16 sm[];
    __nv_bfloat16* Ah = sm;
    __nv_bfloat16* Al = Ah + SM_TILE;
    __nv_bfloat16* Bh = Al + SM_TILE;
    __nv_bfloat16* Bl = Bh + SM_TILE;

    const int tid  = threadIdx.x;
    const int lane = tid & 31;
    const int wid  = tid >> 5;
    const int row0 = blockIdx.x * 128;
    const int col0 = blockIdx.y * 128;

    // ---- stage A: x [128 x 128] fp32 -> hi/lo bf16 ----
#pragma unroll
    for (int i = 0; i < 16; i++) {
        int idx = i * 256 + tid;
        int m = idx >> 5, q = idx & 31;           // q: float4 within row
        float4 v = ((const float4*)(x + (size_t)(row0 + m) * D_))[q];
        __nv_bfloat162 h01 = __floats2bfloat162_rn(v.x, v.y);
        __nv_bfloat162 h23 = __floats2bfloat162_rn(v.z, v.w);
        __nv_bfloat162 l01 = __floats2bfloat162_rn(
            v.x - __bfloat162float(h01.x), v.y - __bfloat162float(h01.y));
        __nv_bfloat162 l23 = __floats2bfloat162_rn(
            v.z - __bfloat162float(h23.x), v.w - __bfloat162float(h23.y));
        uint2 hu, lu;
        hu.x = *(uint32_t*)&h01; hu.y = *(uint32_t*)&h23;
        lu.x = *(uint32_t*)&l01; lu.y = *(uint32_t*)&l23;
        *(uint2*)&Ah[m * PITCH + q * 4] = hu;
        *(uint2*)&Al[m * PITCH + q * 4] = lu;
    }
    // ---- stage B: W^T hi/lo rows j = col0..col0+127 ----
#pragma unroll
    for (int i = 0; i < 8; i++) {
        int idx = i * 256 + tid;
        int n = idx >> 4, q = idx & 15;           // q: uint4 (8 bf16) in row
        uint4 vh = ((const uint4*)(wth + (size_t)(col0 + n) * 128))[q];
        uint4 vl = ((const uint4*)(wtl + (size_t)(col0 + n) * 128))[q];
        *(uint4*)&Bh[n * PITCH + q * 8] = vh;
        *(uint4*)&Bl[n * PITCH + q * 8] = vl;
    }
    __syncthreads();

    const int wm = wid & 1;       // M half (64 rows)
    const int wn = wid >> 1;      // N quarter (32 cols)

    float acc[4][4][4];
#pragma unroll
    for (int mi = 0; mi < 4; mi++)
#pragma unroll
        for (int ni = 0; ni < 4; ni++)
#pragma unroll
            for (int q = 0; q < 4; q++) acc[mi][ni][q] = 0.0f;

    // ldmatrix base addresses (per-lane)
    //   A x4: lanes 0-7 rows 0-7 k0 | 8-15 rows 8-15 k0 | 16-23 rows 0-7 k8 | 24-31 rows 8-15 k8
    const int ar = lane & 15, ah_ = lane >> 4;
    //   B x4: m = lane>>3: {n0-7,k0} {n0-7,k8} {n8-15,k0} {n8-15,k8}
    const int bmat = lane >> 3, brow = lane & 7;
    const int bn = (bmat >> 1) * 8 + brow, bk = (bmat & 1) * 8;

    const uint32_t ah_base = smem_u32(Ah) +
        ((wm * 64 + ar) * PITCH + ah_ * 8) * 2;
    const uint32_t al_base = ah_base + SM_TILE * 2;
    const uint32_t bh_base = smem_u32(Bh) + ((wn * 32 + bn) * PITCH + bk) * 2;
    const uint32_t bl_base = bh_base + SM_TILE * 2;

#pragma unroll
    for (int ks = 0; ks < 8; ks++) {
        uint32_t a_h[4][4], a_l[4][4], b_h[4][2], b_l[4][2];
#pragma unroll
        for (int mi = 0; mi < 4; mi++) {
            uint32_t off = (mi * 16 * PITCH + ks * 16) * 2;
            ldm_x4(a_h[mi][0], a_h[mi][1], a_h[mi][2], a_h[mi][3], ah_base + off);
            ldm_x4(a_l[mi][0], a_l[mi][1], a_l[mi][2], a_l[mi][3], al_base + off);
        }
#pragma unroll
        for (int p = 0; p < 2; p++) {
            uint32_t off = (p * 16 * PITCH + ks * 16) * 2;
            ldm_x4(b_h[2*p][0], b_h[2*p][1], b_h[2*p+1][0], b_h[2*p+1][1],
                   bh_base + off);
            ldm_x4(b_l[2*p][0], b_l[2*p][1], b_l[2*p+1][0], b_l[2*p+1][1],
                   bl_base + off);
        }
#pragma unroll
        for (int mi = 0; mi < 4; mi++)
#pragma unroll
            for (int ni = 0; ni < 4; ni++) {
                mma_bf16(acc[mi][ni], a_h[mi], b_h[ni]);
                mma_bf16(acc[mi][ni], a_h[mi], b_l[ni]);
                mma_bf16(acc[mi][ni], a_l[mi], b_h[ni]);
            }
    }

    // ---- epilogue: bias + direct STG.64 (4-lane groups = 32B sectors) ----
    const int g2 = lane >> 2, t2 = (lane & 3) * 2;
#pragma unroll
    for (int ni = 0; ni < 4; ni++) {
        const int col = col0 + wn * 32 + ni * 8 + t2;
        const float2 bc = *(const float2*)&bias[col];
#pragma unroll
        for (int mi = 0; mi < 4; mi++) {
            const int m = row0 + wm * 64 + mi * 16 + g2;
            float2 v0 = make_float2(acc[mi][ni][0] + bc.x, acc[mi][ni][1] + bc.y);
            float2 v1 = make_float2(acc[mi][ni][2] + bc.x, acc[mi][ni][3] + bc.y);
            *(float2*)&out[(size_t)m * G_ + col] = v0;
            *(float2*)&out[(size_t)(m + 8) * G_ + col] = v1;
        }
    }
}

// ---------------------------------------------------------------------------
// GRU scan (unchanged from R6, 427us): 256 threads, 2 rows/CTA, U in regs.
// ---------------------------------------------------------------------------
__global__ __launch_bounds__(256, 1)
void gru_scan(const float* __restrict__ U, const float* __restrict__ brec,
              const float* __restrict__ xp, float* __restrict__ out)
{
    __shared__ __align__(16) float h_sm[2][2][2][68];
    const int tid  = threadIdx.x;
    const int lane = tid & 31;
    const int kg   = lane >> 4;
    const int u    = (tid >> 5) * 16 + (lane & 15);
    const int kb   = kg * 64;

    u64 w[3][32];
#pragma unroll
    for (int i = 0; i < 32; i++)
#pragma unroll
        for (int c = 0; c < 3; c++)
            w[c][i] = pack2(U[(kb + 2*i) * G_ + u + c*128],
                            U[(kb + 2*i + 1) * G_ + u + c*128]);
    const float bz = brec[u], br_ = brec[u + 128], bh = brec[u + 256];

    const int row = kg;
    const int b0  = blockIdx.x * 2;
    const float* exr = xp + (size_t)(b0 + row) * T_ * G_;
    float* eo = out + (size_t)(b0 + row) * T_ * H_;

    float xz  = exr[u];
    float xr_ = exr[u + 128];
    float xh  = exr[u + 256];
    float hp  = 0.0f;

    if (tid < 128) {
        h_sm[0][0][tid >> 6][tid & 63] = 0.0f;
        h_sm[0][1][tid >> 6][tid & 63] = 0.0f;
    }
    __syncthreads();

    for (int t = 0; t < T_; t++) {
        const int buf = t & 1;
        float nxz = 0.f, nxr = 0.f, nxh = 0.f;
        if (t + 1 < T_) {
            const float* xn = exr + (size_t)(t + 1) * G_;
            nxz = xn[u]; nxr = xn[u + 128]; nxh = xn[u + 256];
        }

        u64 a00 = 0, a01 = 0, a02 = 0, a10 = 0, a11 = 0, a12 = 0;
        const float* h0p = &h_sm[buf][0][kg][0];
        const float* h1p = &h_sm[buf][1][kg][0];
#pragma unroll
        for (int i2 = 0; i2 < 16; i2++) {
            ulonglong2 h0 = *(const ulonglong2*)&h0p[4*i2];
            ulonglong2 h1 = *(const ulonglong2*)&h1p[4*i2];
            a00 = fma2(h0.x, w[0][2*i2],     a00);
            a00 = fma2(h0.y, w[0][2*i2 + 1], a00);
            a01 = fma2(h0.x, w[1][2*i2],     a01);
            a01 = fma2(h0.y, w[1][2*i2 + 1], a01);
            a02 = fma2(h0.x, w[2][2*i2],     a02);
            a02 = fma2(h0.y, w[2][2*i2 + 1], a02);
            a10 = fma2(h1.x, w[0][2*i2],     a10);
            a10 = fma2(h1.y, w[0][2*i2 + 1], a10);
            a11 = fma2(h1.x, w[1][2*i2],     a11);
            a11 = fma2(h1.y, w[1][2*i2 + 1], a11);
            a12 = fma2(h1.x, w[2][2*i2],     a12);
            a12 = fma2(h1.y, w[2][2*i2 + 1], a12);
        }
        float s[2][3];
        { float a, b;
          unpack2(a00, a, b); s[0][0] = a + b;
          unpack2(a01, a, b); s[0][1] = a + b;
          unpack2(a02, a, b); s[0][2] = a + b;
          unpack2(a10, a, b); s[1][0] = a + b;
          unpack2(a11, a, b); s[1][1] = a + b;
          unpack2(a12, a, b); s[1][2] = a + b; }

        float own0 = kg ? s[1][0] : s[0][0];
        float own1 = kg ? s[1][1] : s[0][1];
        float own2 = kg ? s[1][2] : s[0][2];
        float oth0 = kg ? s[0][0] : s[1][0];
        float oth1 = kg ? s[0][1] : s[1][1];
        float oth2 = kg ? s[0][2] : s[1][2];
        float rz = own0 + __shfl_xor_sync(0xffffffffu, oth0, 16) + bz;
        float rr = own1 + __shfl_xor_sync(0xffffffffu, oth1, 16) + br_;
        float rh = own2 + __shfl_xor_sync(0xffffffffu, oth2, 16) + bh;

        float z  = sigf(xz + rz);
        float rg = sigf(xr_ + rr);
        float hh = tanh_fast(xh + rg * rh);
        float hn = hh + z * (hp - hh);
        hp = hn;
        h_sm[buf ^ 1][row][u >> 6][u & 63] = hn;
        eo[(size_t)t * H_ + u] = hn;
        xz = nxz; xr_ = nxr; xh = nxh;
        __syncthreads();
    }
}

// ---------------------------------------------------------------------------
extern "C" void kernel_launch(void* const* d_in, const int* in_sizes, int n_in,
                              void* d_out, int out_size)
{
    const float* x  = (const float*)d_in[0];
    const float* W0 = (const float*)d_in[1];
    const float* U0 = (const float*)d_in[2];
    const float* b0 = (const float*)d_in[3];
    const float* W1 = (const float*)d_in[4];
    const float* U1 = (const float*)d_in[5];
    const float* b1 = (const float*)d_in[6];
    float* out = (float*)d_out;

    float *xp, *h0;
    __nv_bfloat16 *wth, *wtl;
    cudaGetSymbolAddress((void**)&xp,  g_xp);
    cudaGetSymbolAddress((void**)&h0,  g_h0);
    cudaGetSymbolAddress((void**)&wth, g_wth);
    cudaGetSymbolAddress((void**)&wtl, g_wtl);

    cudaFuncSetAttribute(proj_mma, cudaFuncAttributeMaxDynamicSharedMemorySize,
                         SMEM_PROJ);

    dim3 pgrid(BT_ / 128, 3);

    // layer 0
    prep_w<<<192, 256>>>(W0, wth, wtl);
    proj_mma<<<pgrid, 256, SMEM_PROJ>>>(x, wth, wtl, b0, xp);
    gru_scan<<<B_ / 2, 256>>>(U0, b0 + G_, xp, h0);
    // layer 1
    prep_w<<<192, 256>>>(W1, wth, wtl);
    proj_mma<<<pgrid, 256, SMEM_PROJ>>>(h0, wth, wtl, b1, xp);
    gru_scan<<<B_ / 2, 256>>>(U1, b1 + G_, xp, out);
}